// round 15
// baseline (speedup 1.0000x reference)
#include <cuda_runtime.h>
#include <cuda_fp16.h>
#include <cstdint>
#include <cstddef>

#define BATCH 1024
#define SIZE  65536
#define DIM   512
#define SPLITS 32
#define KSPLIT (SIZE / SPLITS)        // 2048

#define RBYTES 64                     // dense 32-half rows, 4-slot XOR swizzle (key row&3)
#define TILE_BYTES (128 * RBYTES)     // 8192
#define STAGE_BYTES (2 * TILE_BYTES)  // 16384 (A+B)
#define NSTAGE 3
#define SMEM_BYTES (NSTAGE * STAGE_BYTES) // 49152 -> occ 4 smem-feasible
#define THREADS 256                   // 8 warps, warp grid 2 (wm) x 4 (wn), warp tile 64x32
#define NCH1 (DIM / 32)               // 16
#define NCH2 (KSPLIT / 32)            // 64

// ---------------- device scratch (allocation-free) ----------------
__device__ float g_minv[SIZE];
__device__ float g_ssq[(size_t)SIZE * 16];                     //   4 MB partial sumsq
__device__ __align__(16) __half g_xp[(size_t)BATCH * DIM];     //   1 MB
__device__ __align__(16) __half g_mb1[(size_t)SIZE * DIM];     //  64 MB (GEMM1 B)
__device__ __align__(16) __half g_mbT[(size_t)DIM * SIZE];     //  64 MB (GEMM2 B)
__device__ __align__(16) __half g_P[(size_t)BATCH * SIZE];     // 128 MB (GEMM2 A)
__device__ float g_Lpart[(size_t)(SIZE / 128) * BATCH];        //   2 MB
__device__ float g_part2[(size_t)SPLITS * BATCH * DIM];        //  64 MB

// ---------------- helpers ----------------
__device__ __forceinline__ uint32_t smem_to_u32(const void* p) {
    uint32_t a;
    asm("{ .reg .u64 t; cvta.to.shared.u64 t, %1; cvt.u32.u64 %0, t; }" : "=r"(a) : "l"(p));
    return a;
}
__device__ __forceinline__ void cp16(uint32_t s, const void* g) {
    asm volatile("cp.async.cg.shared.global [%0], [%1], 16;" :: "r"(s), "l"(g));
}
__device__ __forceinline__ void cp_commit() { asm volatile("cp.async.commit_group;"); }
__device__ __forceinline__ float ex2f(float x) {
    float r;
    asm("ex2.approx.f32 %0, %1;" : "=f"(r) : "f"(x));
    return r;
}

// k-permutation within each 16-half group: thread tg's fragment halfs
// {2tg,2tg+1,2tg+8,2tg+9} land at phys [4tg,4tg+4): one LDS.64 per fragment.
__device__ __forceinline__ int pairphys(int tp) {
    return ((tp >> 3) << 4) + ((tp & 3) << 2) + (((tp >> 2) & 1) << 1);
}

__device__ __forceinline__ void mma_f16(float* c, uint2 alo, uint2 ahi, uint2 b) {
    asm volatile(
        "mma.sync.aligned.m16n8k16.row.col.f32.f16.f16.f32 "
        "{%0,%1,%2,%3}, {%4,%5,%6,%7}, {%8,%9}, {%0,%1,%2,%3};"
        : "+f"(c[0]), "+f"(c[1]), "+f"(c[2]), "+f"(c[3])
        : "r"(alo.x), "r"(ahi.x), "r"(alo.y), "r"(ahi.y), "r"(b.x), "r"(b.y));
}

// ---------------- kernel 1: pack x -> fp16 (norm fused), k-perm ----------------
__global__ void pack_x_kernel(const float* __restrict__ x) {
    int m = blockIdx.x * 8 + (threadIdx.x >> 5);   // warp per row
    int l = threadIdx.x & 31;
    const float4* a = reinterpret_cast<const float4*>(x + (size_t)m * DIM);
    float4 v[4]; float ss = 0.f;
#pragma unroll
    for (int j = 0; j < 4; ++j) {
        v[j] = a[l + 32 * j];
        ss += v[j].x * v[j].x + v[j].y * v[j].y + v[j].z * v[j].z + v[j].w * v[j].w;
    }
#pragma unroll
    for (int o = 16; o; o >>= 1) ss += __shfl_xor_sync(0xffffffffu, ss, o);
    float s = 8.0f * rsqrtf(fmaxf(ss, 1e-24f));
#pragma unroll
    for (int j = 0; j < 4; ++j) {
        int p0 = 2 * (l + 32 * j);
        int o0 = ((p0 >> 3) << 4) + pairphys(p0 & 7);
        int o1 = (((p0 + 1) >> 3) << 4) + pairphys((p0 + 1) & 7);
        *(__half2*)&g_xp[(size_t)m * DIM + o0] = __floats2half2_rn(v[j].x * s, v[j].y * s);
        *(__half2*)&g_xp[(size_t)m * DIM + o1] = __floats2half2_rn(v[j].z * s, v[j].w * s);
    }
}

// ---------------- kernel 2: pack mb -> g_mb1 + g_mbT + partial sumsq ----------------
__global__ void pack_mb_kernel(const float* __restrict__ mbk) {
    __shared__ float t[32][33];
    int s0 = blockIdx.x << 5, d0 = blockIdx.y << 5;
    int tp = threadIdx.x & 15, ty = threadIdx.x >> 4;   // 256 threads
    int pg = pairphys(tp & 7) + ((tp >> 3) << 4);
    float ss[2];
#pragma unroll
    for (int k = 0; k < 2; ++k) {
        int r = ty + 16 * k;
        float2 v = *(const float2*)&mbk[(size_t)(s0 + r) * DIM + d0 + 2 * tp];
        t[r][2 * tp] = v.x; t[r][2 * tp + 1] = v.y;
        *(__half2*)&g_mb1[(size_t)(s0 + r) * DIM + d0 + pg] = __float22half2_rn(v);
        ss[k] = v.x * v.x + v.y * v.y;
    }
#pragma unroll
    for (int o = 8; o; o >>= 1) {       // reduce across 16 same-ty lanes
        ss[0] += __shfl_xor_sync(0xffffffffu, ss[0], o);
        ss[1] += __shfl_xor_sync(0xffffffffu, ss[1], o);
    }
    if (tp == 0) {
        g_ssq[(size_t)(s0 + ty) * 16 + blockIdx.y] = ss[0];
        g_ssq[(size_t)(s0 + ty + 16) * 16 + blockIdx.y] = ss[1];
    }
    __syncthreads();
#pragma unroll
    for (int k = 0; k < 2; ++k) {
        int dd = ty + 16 * k;
        float2 v = make_float2(t[2 * tp][dd], t[2 * tp + 1][dd]);
        *(__half2*)&g_mbT[(size_t)(d0 + dd) * SIZE + s0 + pg] = __float22half2_rn(v);
    }
}

// ---------------- kernel 3: reduce 16 partials -> inverse norm ----------------
__global__ void mbnorm_reduce_kernel() {
    int r = blockIdx.x * 256 + threadIdx.x;
    const float4* p = (const float4*)&g_ssq[(size_t)r * 16];
    float4 a = p[0], b = p[1], c = p[2], d = p[3];
    float s = (a.x + a.y + a.z + a.w) + (b.x + b.y + b.z + b.w)
            + (c.x + c.y + c.z + c.w) + (d.x + d.y + d.z + d.w);
    g_minv[r] = rsqrtf(fmaxf(s, 1e-24f));
}

// ---------------- GEMM machinery: 8 warps, warp tile 64x32, 32-k chunks ----------
// Swizzle: slot' = slot ^ (row & 3) on 4 slots/row — verified conflict-free per
// 16-lane LDS.64 phase (this is the proven R9 layout; packs match it).
__device__ __forceinline__ void load_tiles(uint32_t sbase,
                                           const __half* __restrict__ Ag,
                                           const __half* __restrict__ Bg,
                                           size_t arow, size_t brow, int kpos, int tid) {
#pragma unroll
    for (int j = 0; j < 2; ++j) {                 // A: 128 rows x 4 granules = 512
        int i = tid + THREADS * j;
        int row = i >> 2, gg = i & 3;
        cp16(sbase + row * RBYTES + ((gg ^ (row & 3)) << 4),
             Ag + (size_t)row * arow + kpos + gg * 8);
    }
#pragma unroll
    for (int j = 0; j < 2; ++j) {                 // B
        int i = tid + THREADS * j;
        int row = i >> 2, gg = i & 3;
        cp16(sbase + TILE_BYTES + row * RBYTES + ((gg ^ (row & 3)) << 4),
             Bg + (size_t)row * brow + kpos + gg * 8);
    }
}

__device__ __forceinline__ void compute_chunk(const char* __restrict__ As,
                                              const char* __restrict__ Bs,
                                              int wm, int wn, int g, int tg,
                                              float c[4][4][4]) {
    const char* Aw = As + (wm * 64 + g) * RBYTES;
    const char* Bw = Bs + (wn * 32 + g) * RBYTES;
    const int gx = g & 3;
#pragma unroll
    for (int j = 0; j < 2; ++j) {                 // two k16 steps per 32-k chunk
        int boff = ((((tg >> 1) + 2 * j) ^ gx) << 4) + ((tg & 1) << 3);
        uint2 alo[4], ahi[4], bf[4];
#pragma unroll
        for (int mt = 0; mt < 4; ++mt) {
            alo[mt] = *(const uint2*)(Aw + (mt * 16) * RBYTES + boff);
            ahi[mt] = *(const uint2*)(Aw + (mt * 16 + 8) * RBYTES + boff);
        }
#pragma unroll
        for (int nt = 0; nt < 4; ++nt)
            bf[nt] = *(const uint2*)(Bw + (nt * 8) * RBYTES + boff);
#pragma unroll
        for (int mt = 0; mt < 4; ++mt)
#pragma unroll
            for (int nt = 0; nt < 4; ++nt)
                mma_f16(c[mt][nt], alo[mt], ahi[mt], bf[nt]);
    }
}

__device__ __forceinline__ void gemm_mainloop(char* smc, uint32_t sm32,
                                              const __half* __restrict__ Ag,
                                              const __half* __restrict__ Bg,
                                              size_t arow, size_t brow,
                                              int kbase, int nch, int tid,
                                              int wm, int wn, int g, int tg,
                                              float c[4][4][4]) {
#pragma unroll
    for (int s = 0; s < 2; ++s) {
        load_tiles(sm32 + s * STAGE_BYTES, Ag, Bg, arow, brow, kbase + s * 32, tid);
        cp_commit();
    }
    for (int t = 0; t < nch; ++t) {
        if (t + 2 < nch) asm volatile("cp.async.wait_group 1;");
        else             asm volatile("cp.async.wait_group 0;");
        __syncthreads();   // stage t ready; stage (t+2)%3 free (consumed at t-1)
        if (t + 2 < nch) {
            load_tiles(sm32 + ((t + 2) % 3) * STAGE_BYTES, Ag, Bg, arow, brow,
                       kbase + (t + 2) * 32, tid);
            cp_commit();
        }
        const char* As = smc + (t % 3) * STAGE_BYTES;
        compute_chunk(As, As + TILE_BYTES, wm, wn, g, tg, c);
    }
}

// ---------------- kernel 4: GEMM1 sims + exp epilogue -> g_P (direct), g_Lpart ----------
__global__ __launch_bounds__(THREADS, 4) void gemm1_kernel() {
    extern __shared__ char smc[];
    uint32_t sm32 = smem_to_u32(smc);
    int tid = threadIdx.x, lane = tid & 31, w = tid >> 5;
    int wm = w & 1, wn = w >> 1, g = lane >> 2, tg = lane & 3;
    int mblk = blockIdx.x, nblk = blockIdx.y;

    float c[4][4][4];
#pragma unroll
    for (int mt = 0; mt < 4; ++mt)
#pragma unroll
        for (int nt = 0; nt < 4; ++nt)
#pragma unroll
            for (int i = 0; i < 4; ++i) c[mt][nt][i] = 0.f;

    gemm_mainloop(smc, sm32,
                  g_xp + (size_t)mblk * 128 * DIM,
                  g_mb1 + (size_t)nblk * 128 * DIM,
                  DIM, DIM, 0, NCH1, tid, wm, wn, g, tg, c);

    __syncthreads();                         // tiles dead; reuse smem
    float* smL = (float*)smc;                // [4][128] = 2048 B
    float* minv_s = (float*)(smc + 2048);    // [128]
    if (tid < 128) minv_s[tid] = g_minv[nblk * 128 + tid] * 1.44269504f; // fold log2e
    __syncthreads();

    // exp (single ex2) + direct half2 stores into perm16 phys layout
    float sl[4], sh[4];
#pragma unroll
    for (int mt = 0; mt < 4; ++mt) { sl[mt] = 0.f; sh[mt] = 0.f; }
#pragma unroll
    for (int mt = 0; mt < 4; ++mt) {
        int row0 = mblk * 128 + wm * 64 + mt * 16 + g;
        size_t b0 = (size_t)row0 * SIZE;
        size_t b8 = (size_t)(row0 + 8) * SIZE;
#pragma unroll
        for (int nt = 0; nt < 4; ++nt) {
            int col0 = wn * 32 + nt * 8 + 2 * tg;     // logical col in [0,128)
            float m0 = minv_s[col0], m1 = minv_s[col0 + 1];
            float e0 = ex2f(c[mt][nt][0] * m0);
            float e1 = ex2f(c[mt][nt][1] * m1);
            float e2 = ex2f(c[mt][nt][2] * m0);
            float e3 = ex2f(c[mt][nt][3] * m1);
            sl[mt] += e0 + e1;
            sh[mt] += e2 + e3;
            // phys col (perm16): group = wn*2 + nt/2, in-group = 4tg + 2*(nt&1)
            size_t scol = (size_t)nblk * 128 + (((wn << 1) + (nt >> 1)) << 4)
                        + 4 * tg + 2 * (nt & 1);
            *(__half2*)&g_P[b0 + scol] = __floats2half2_rn(e0, e1);
            *(__half2*)&g_P[b8 + scol] = __floats2half2_rn(e2, e3);
        }
    }
#pragma unroll
    for (int mt = 0; mt < 4; ++mt) {
        float vl = sl[mt], vh = sh[mt];
        vl += __shfl_xor_sync(0xffffffffu, vl, 1);
        vl += __shfl_xor_sync(0xffffffffu, vl, 2);
        vh += __shfl_xor_sync(0xffffffffu, vh, 1);
        vh += __shfl_xor_sync(0xffffffffu, vh, 2);
        if (tg == 0) {
            smL[wn * 128 + wm * 64 + mt * 16 + g] = vl;
            smL[wn * 128 + wm * 64 + mt * 16 + g + 8] = vh;
        }
    }
    __syncthreads();
    if (tid < 128)
        g_Lpart[(size_t)nblk * BATCH + mblk * 128 + tid] =
            (smL[tid] + smL[128 + tid]) + (smL[256 + tid] + smL[384 + tid]);
}

// ---------------- kernel 5: GEMM2 O = P @ mb (split-K partials) ----------------
__global__ __launch_bounds__(THREADS, 4) void gemm2_kernel() {
    extern __shared__ char smc[];
    uint32_t sm32 = smem_to_u32(smc);
    int tid = threadIdx.x, lane = tid & 31, w = tid >> 5;
    int wm = w & 1, wn = w >> 1, g = lane >> 2, tg = lane & 3;
    int mblk = blockIdx.x, nblk = blockIdx.y, sp = blockIdx.z;

    float c[4][4][4];
#pragma unroll
    for (int mt = 0; mt < 4; ++mt)
#pragma unroll
        for (int nt = 0; nt < 4; ++nt)
#pragma unroll
            for (int i = 0; i < 4; ++i) c[mt][nt][i] = 0.f;

    gemm_mainloop(smc, sm32,
                  g_P + (size_t)mblk * 128 * SIZE,
                  g_mbT + (size_t)nblk * 128 * SIZE,
                  SIZE, SIZE, sp * KSPLIT, NCH2, tid, wm, wn, g, tg, c);

#pragma unroll
    for (int mt = 0; mt < 4; ++mt) {
        int b = mblk * 128 + wm * 64 + mt * 16 + g;
#pragma unroll
        for (int nt = 0; nt < 4; ++nt) {
            int d = nblk * 128 + wn * 32 + nt * 8 + 2 * tg;
            float* dst = &g_part2[((size_t)sp * BATCH + b) * DIM + d];
            *(float2*)dst = make_float2(c[mt][nt][0], c[mt][nt][1]);
            *(float2*)(dst + (size_t)8 * DIM) = make_float2(c[mt][nt][2], c[mt][nt][3]);
        }
    }
}

// ---------------- kernel 6: combine split-K partials, divide by L ----------------
__global__ void combine_kernel(float* __restrict__ out) {
    int b = blockIdx.x, tid = threadIdx.x;   // 128 threads
    __shared__ float red[128];
    float ls = 0.f;
#pragma unroll
    for (int k = 0; k < 4; ++k) ls += g_Lpart[(size_t)(k * 128 + tid) * BATCH + b];
    red[tid] = ls;
    __syncthreads();
    for (int o = 64; o; o >>= 1) { if (tid < o) red[tid] += red[tid + o]; __syncthreads(); }
    float invL = 1.0f / red[0];
    int d = tid * 4;
    float4 acc = make_float4(0.f, 0.f, 0.f, 0.f);
#pragma unroll
    for (int sp = 0; sp < SPLITS; ++sp) {
        const float4 v = *(const float4*)&g_part2[((size_t)sp * BATCH + b) * DIM + d];
        acc.x += v.x; acc.y += v.y; acc.z += v.z; acc.w += v.w;
    }
    acc.x *= invL; acc.y *= invL; acc.z *= invL; acc.w *= invL;
    *(float4*)&out[(size_t)b * DIM + d] = acc;
}

// ---------------------------------------------------------------------------
extern "C" void kernel_launch(void* const* d_in, const int* in_sizes, int n_in,
                              void* d_out, int out_size) {
    const float* x = (const float*)d_in[0];
    const float* mb = (const float*)d_in[1];
    float* out = (float*)d_out;
    (void)in_sizes; (void)n_in; (void)out_size;

    cudaFuncSetAttribute(gemm1_kernel, cudaFuncAttributeMaxDynamicSharedMemorySize, SMEM_BYTES);
    cudaFuncSetAttribute(gemm2_kernel, cudaFuncAttributeMaxDynamicSharedMemorySize, SMEM_BYTES);

    pack_x_kernel<<<BATCH / 8, 256>>>(x);
    pack_mb_kernel<<<dim3(SIZE / 32, DIM / 32), 256>>>(mb);
    mbnorm_reduce_kernel<<<SIZE / 256, 256>>>();
    gemm1_kernel<<<dim3(BATCH / 128, SIZE / 128), THREADS, SMEM_BYTES>>>();
    gemm2_kernel<<<dim3(BATCH / 128, DIM / 128, SPLITS), THREADS, SMEM_BYTES>>>();
    combine_kernel<<<BATCH, 128>>>(out);
}

// round 16
// speedup vs baseline: 3.4738x; 3.4738x over previous
#include <cuda_runtime.h>
#include <cuda_fp16.h>
#include <cstdint>
#include <cstddef>

#define BATCH 1024
#define SIZE  65536
#define DIM   512
#define SPLITS 32
#define KSPLIT (SIZE / SPLITS)        // 2048

#define RBYTES 128                    // dense 64-half rows, even-key XOR swizzle
#define AROWS 64                      // CTA tile M (A rows)
#define BROWS 128                     // CTA tile N (B rows)
#define TILE_A_BYTES (AROWS * RBYTES) // 8192
#define TILE_B_BYTES (BROWS * RBYTES) // 16384
#define STAGE_BYTES (TILE_A_BYTES + TILE_B_BYTES) // 24576
#define NSTAGE 2
#define SMEM_BYTES (NSTAGE * STAGE_BYTES) // 49152 -> 4 CTAs/SM smem-feasible
#define THREADS 64                    // 2 warps: wn = warp id, warp tile 64x64
#define NCH1 (DIM / 64)               // 8
#define NCH2 (KSPLIT / 64)            // 32

// ---------------- device scratch (allocation-free) ----------------
__device__ float g_minv[SIZE];
__device__ float g_ssq[(size_t)SIZE * 16];                     //   4 MB partial sumsq
__device__ __align__(16) __half g_xp[(size_t)BATCH * DIM];     //   1 MB
__device__ __align__(16) __half g_mb1[(size_t)SIZE * DIM];     //  64 MB (GEMM1 B)
__device__ __align__(16) __half g_mbT[(size_t)DIM * SIZE];     //  64 MB (GEMM2 B)
__device__ __align__(16) __half g_P[(size_t)BATCH * SIZE];     // 128 MB (GEMM2 A)
__device__ float g_Lpart[(size_t)(SIZE / 128) * BATCH];        //   2 MB
__device__ float g_part2[(size_t)SPLITS * BATCH * DIM];        //  64 MB

// ---------------- helpers ----------------
__device__ __forceinline__ uint32_t smem_to_u32(const void* p) {
    uint32_t a;
    asm("{ .reg .u64 t; cvta.to.shared.u64 t, %1; cvt.u32.u64 %0, t; }" : "=r"(a) : "l"(p));
    return a;
}
__device__ __forceinline__ void cp16(uint32_t s, const void* g) {
    asm volatile("cp.async.cg.shared.global [%0], [%1], 16;" :: "r"(s), "l"(g));
}
__device__ __forceinline__ void cp_commit() { asm volatile("cp.async.commit_group;"); }
__device__ __forceinline__ float ex2f(float x) {
    float r;
    asm("ex2.approx.f32 %0, %1;" : "=f"(r) : "f"(x));
    return r;
}

// k-permutation within each 16-half group: thread tg's fragment halfs
// {2tg,2tg+1,2tg+8,2tg+9} land at phys [4tg,4tg+4): one LDS.64 per fragment.
__device__ __forceinline__ int pairphys(int tp) {
    return ((tp >> 3) << 4) + ((tp & 3) << 2) + (((tp >> 2) & 1) << 1);
}

__device__ __forceinline__ void mma_f16(float* c, uint2 alo, uint2 ahi, uint2 b) {
    asm volatile(
        "mma.sync.aligned.m16n8k16.row.col.f32.f16.f16.f32 "
        "{%0,%1,%2,%3}, {%4,%5,%6,%7}, {%8,%9}, {%0,%1,%2,%3};"
        : "+f"(c[0]), "+f"(c[1]), "+f"(c[2]), "+f"(c[3])
        : "r"(alo.x), "r"(ahi.x), "r"(alo.y), "r"(ahi.y), "r"(b.x), "r"(b.y));
}

// ---------------- kernel 1: pack x -> fp16 (norm fused), k-perm ----------------
__global__ void pack_x_kernel(const float* __restrict__ x) {
    int m = blockIdx.x * 8 + (threadIdx.x >> 5);   // warp per row
    int l = threadIdx.x & 31;
    const float4* a = reinterpret_cast<const float4*>(x + (size_t)m * DIM);
    float4 v[4]; float ss = 0.f;
#pragma unroll
    for (int j = 0; j < 4; ++j) {
        v[j] = a[l + 32 * j];
        ss += v[j].x * v[j].x + v[j].y * v[j].y + v[j].z * v[j].z + v[j].w * v[j].w;
    }
#pragma unroll
    for (int o = 16; o; o >>= 1) ss += __shfl_xor_sync(0xffffffffu, ss, o);
    float s = 8.0f * rsqrtf(fmaxf(ss, 1e-24f));
#pragma unroll
    for (int j = 0; j < 4; ++j) {
        int p0 = 2 * (l + 32 * j);
        int o0 = ((p0 >> 3) << 4) + pairphys(p0 & 7);
        int o1 = (((p0 + 1) >> 3) << 4) + pairphys((p0 + 1) & 7);
        *(__half2*)&g_xp[(size_t)m * DIM + o0] = __floats2half2_rn(v[j].x * s, v[j].y * s);
        *(__half2*)&g_xp[(size_t)m * DIM + o1] = __floats2half2_rn(v[j].z * s, v[j].w * s);
    }
}

// ---------------- kernel 2: pack mb -> g_mb1 + g_mbT + partial sumsq ----------------
__global__ void pack_mb_kernel(const float* __restrict__ mbk) {
    __shared__ float t[32][33];
    int s0 = blockIdx.x << 5, d0 = blockIdx.y << 5;
    int tp = threadIdx.x & 15, ty = threadIdx.x >> 4;   // 256 threads
    int pg = pairphys(tp & 7) + ((tp >> 3) << 4);
    float ss[2];
#pragma unroll
    for (int k = 0; k < 2; ++k) {
        int r = ty + 16 * k;
        float2 v = *(const float2*)&mbk[(size_t)(s0 + r) * DIM + d0 + 2 * tp];
        t[r][2 * tp] = v.x; t[r][2 * tp + 1] = v.y;
        *(__half2*)&g_mb1[(size_t)(s0 + r) * DIM + d0 + pg] = __float22half2_rn(v);
        ss[k] = v.x * v.x + v.y * v.y;
    }
#pragma unroll
    for (int o = 8; o; o >>= 1) {       // reduce across 16 same-ty lanes
        ss[0] += __shfl_xor_sync(0xffffffffu, ss[0], o);
        ss[1] += __shfl_xor_sync(0xffffffffu, ss[1], o);
    }
    if (tp == 0) {
        g_ssq[(size_t)(s0 + ty) * 16 + blockIdx.y] = ss[0];
        g_ssq[(size_t)(s0 + ty + 16) * 16 + blockIdx.y] = ss[1];
    }
    __syncthreads();
#pragma unroll
    for (int k = 0; k < 2; ++k) {
        int dd = ty + 16 * k;
        float2 v = make_float2(t[2 * tp][dd], t[2 * tp + 1][dd]);
        *(__half2*)&g_mbT[(size_t)(d0 + dd) * SIZE + s0 + pg] = __float22half2_rn(v);
    }
}

// ---------------- kernel 3: reduce 16 partials -> inverse norm ----------------
__global__ void mbnorm_reduce_kernel() {
    int r = blockIdx.x * 256 + threadIdx.x;
    const float4* p = (const float4*)&g_ssq[(size_t)r * 16];
    float4 a = p[0], b = p[1], c = p[2], d = p[3];
    float s = (a.x + a.y + a.z + a.w) + (b.x + b.y + b.z + b.w)
            + (c.x + c.y + c.z + c.w) + (d.x + d.y + d.z + d.w);
    g_minv[r] = rsqrtf(fmaxf(s, 1e-24f));
}

// ---------------- GEMM machinery: 2 warps/CTA, CTA tile 64x128, 64-k chunks ----------
// Swizzle: chunk' = chunk ^ ((row & 3) << 1) — verified conflict-free (R14).
__device__ __forceinline__ void load_tiles(uint32_t sbase,
                                           const __half* __restrict__ Ag,
                                           const __half* __restrict__ Bg,
                                           size_t arow, size_t brow, int kpos, int tid) {
#pragma unroll
    for (int j = 0; j < 8; ++j) {                 // A: 64 rows x 8 granules = 512
        int i = tid + THREADS * j;
        int row = i >> 3, gg = i & 7;
        cp16(sbase + row * RBYTES + ((gg ^ ((row & 3) << 1)) << 4),
             Ag + (size_t)row * arow + kpos + gg * 8);
    }
#pragma unroll
    for (int j = 0; j < 16; ++j) {                // B: 128 rows x 8 granules = 1024
        int i = tid + THREADS * j;
        int row = i >> 3, gg = i & 7;
        cp16(sbase + TILE_A_BYTES + row * RBYTES + ((gg ^ ((row & 3) << 1)) << 4),
             Bg + (size_t)row * brow + kpos + gg * 8);
    }
}

__device__ __forceinline__ void compute_chunk(const char* __restrict__ As,
                                              const char* __restrict__ Bs,
                                              int wn, int g, int tg,
                                              float c[4][8][4]) {
    const char* Aw = As + g * RBYTES;
    const char* Bw = Bs + (wn * 64 + g) * RBYTES;
    const int gx = (g & 3) << 1;
#pragma unroll
    for (int j = 0; j < 4; ++j) {                 // four k16 steps per 64-k chunk
        int boff = ((((tg >> 1) + 2 * j) ^ gx) << 4) + ((tg & 1) << 3);
        uint2 alo[4], ahi[4], bf[8];
#pragma unroll
        for (int mt = 0; mt < 4; ++mt) {
            alo[mt] = *(const uint2*)(Aw + (mt * 16) * RBYTES + boff);
            ahi[mt] = *(const uint2*)(Aw + (mt * 16 + 8) * RBYTES + boff);
        }
#pragma unroll
        for (int nt = 0; nt < 8; ++nt)
            bf[nt] = *(const uint2*)(Bw + (nt * 8) * RBYTES + boff);
#pragma unroll
        for (int mt = 0; mt < 4; ++mt)
#pragma unroll
            for (int nt = 0; nt < 8; ++nt)
                mma_f16(c[mt][nt], alo[mt], ahi[mt], bf[nt]);
    }
}

__device__ __forceinline__ void gemm_mainloop(char* smc, uint32_t sm32,
                                              const __half* __restrict__ Ag,
                                              const __half* __restrict__ Bg,
                                              size_t arow, size_t brow,
                                              int kbase, int nch, int tid,
                                              int wn, int g, int tg,
                                              float c[4][8][4]) {
    load_tiles(sm32, Ag, Bg, arow, brow, kbase, tid);
    cp_commit();
    for (int t = 0; t < nch; ++t) {
        asm volatile("cp.async.wait_group 0;");   // stage t data committed (this thread)
        __syncthreads();                          // all threads' data in; buf (t+1)&1 free
        if (t + 1 < nch) {
            load_tiles(sm32 + ((t + 1) & 1) * STAGE_BYTES, Ag, Bg, arow, brow,
                       kbase + (t + 1) * 64, tid);
            cp_commit();                          // overlaps with compute(t)
        }
        const char* As = smc + (t & 1) * STAGE_BYTES;
        compute_chunk(As, As + TILE_A_BYTES, wn, g, tg, c);
    }
}

// ---------------- kernel 4: GEMM1 sims + exp epilogue -> g_P (direct), g_Lpart ----------
__global__ __launch_bounds__(THREADS, 4) void gemm1_kernel() {
    extern __shared__ char smc[];
    uint32_t sm32 = smem_to_u32(smc);
    int tid = threadIdx.x, lane = tid & 31;
    int wn = tid >> 5, g = lane >> 2, tg = lane & 3;
    int mblk = blockIdx.x, nblk = blockIdx.y;

    float c[4][8][4];
#pragma unroll
    for (int mt = 0; mt < 4; ++mt)
#pragma unroll
        for (int nt = 0; nt < 8; ++nt)
#pragma unroll
            for (int i = 0; i < 4; ++i) c[mt][nt][i] = 0.f;

    gemm_mainloop(smc, sm32,
                  g_xp + (size_t)mblk * AROWS * DIM,
                  g_mb1 + (size_t)nblk * BROWS * DIM,
                  DIM, DIM, 0, NCH1, tid, wn, g, tg, c);

    __syncthreads();                         // tiles dead; reuse smem
    float* smL = (float*)smc;                // [2][64] = 512 B
    float* minv_s = (float*)(smc + 2048);    // [128]
    minv_s[tid] = g_minv[nblk * 128 + tid] * 1.44269504f;             // fold log2e
    minv_s[tid + 64] = g_minv[nblk * 128 + tid + 64] * 1.44269504f;
    __syncthreads();

    // exp (single ex2) + direct half2 stores into perm16 phys layout
    float sl[4], sh[4];
#pragma unroll
    for (int mt = 0; mt < 4; ++mt) { sl[mt] = 0.f; sh[mt] = 0.f; }
#pragma unroll
    for (int mt = 0; mt < 4; ++mt) {
        int row0 = mblk * AROWS + mt * 16 + g;
        size_t b0 = (size_t)row0 * SIZE;
        size_t b8 = (size_t)(row0 + 8) * SIZE;
#pragma unroll
        for (int nt = 0; nt < 8; ++nt) {
            int col0 = wn * 64 + nt * 8 + 2 * tg;     // logical col in [0,128)
            float m0 = minv_s[col0], m1 = minv_s[col0 + 1];
            float e0 = ex2f(c[mt][nt][0] * m0);
            float e1 = ex2f(c[mt][nt][1] * m1);
            float e2 = ex2f(c[mt][nt][2] * m0);
            float e3 = ex2f(c[mt][nt][3] * m1);
            sl[mt] += e0 + e1;
            sh[mt] += e2 + e3;
            // phys col (perm16): group = wn*4 + nt/2, in-group = 4tg + 2*(nt&1)
            size_t scol = (size_t)nblk * 128 + (((wn << 2) + (nt >> 1)) << 4)
                        + 4 * tg + 2 * (nt & 1);
            *(__half2*)&g_P[b0 + scol] = __floats2half2_rn(e0, e1);
            *(__half2*)&g_P[b8 + scol] = __floats2half2_rn(e2, e3);
        }
    }
#pragma unroll
    for (int mt = 0; mt < 4; ++mt) {
        float vl = sl[mt], vh = sh[mt];
        vl += __shfl_xor_sync(0xffffffffu, vl, 1);
        vl += __shfl_xor_sync(0xffffffffu, vl, 2);
        vh += __shfl_xor_sync(0xffffffffu, vh, 1);
        vh += __shfl_xor_sync(0xffffffffu, vh, 2);
        if (tg == 0) {
            smL[wn * 64 + mt * 16 + g] = vl;
            smL[wn * 64 + mt * 16 + g + 8] = vh;
        }
    }
    __syncthreads();
    g_Lpart[(size_t)nblk * BATCH + mblk * AROWS + tid] = smL[tid] + smL[64 + tid];
}

// ---------------- kernel 5: GEMM2 O = P @ mb (split-K partials) ----------------
__global__ __launch_bounds__(THREADS, 4) void gemm2_kernel() {
    extern __shared__ char smc[];
    uint32_t sm32 = smem_to_u32(smc);
    int tid = threadIdx.x, lane = tid & 31;
    int wn = tid >> 5, g = lane >> 2, tg = lane & 3;
    int mblk = blockIdx.x, nblk = blockIdx.y, sp = blockIdx.z;

    float c[4][8][4];
#pragma unroll
    for (int mt = 0; mt < 4; ++mt)
#pragma unroll
        for (int nt = 0; nt < 8; ++nt)
#pragma unroll
            for (int i = 0; i < 4; ++i) c[mt][nt][i] = 0.f;

    gemm_mainloop(smc, sm32,
                  g_P + (size_t)mblk * AROWS * SIZE,
                  g_mbT + (size_t)nblk * BROWS * SIZE,
                  SIZE, SIZE, sp * KSPLIT, NCH2, tid, wn, g, tg, c);

#pragma unroll
    for (int mt = 0; mt < 4; ++mt) {
        int b = mblk * AROWS + mt * 16 + g;
#pragma unroll
        for (int nt = 0; nt < 8; ++nt) {
            int d = nblk * BROWS + wn * 64 + nt * 8 + 2 * tg;
            float* dst = &g_part2[((size_t)sp * BATCH + b) * DIM + d];
            *(float2*)dst = make_float2(c[mt][nt][0], c[mt][nt][1]);
            *(float2*)(dst + (size_t)8 * DIM) = make_float2(c[mt][nt][2], c[mt][nt][3]);
        }
    }
}

// ---------------- kernel 6: combine split-K partials, divide by L ----------------
__global__ void combine_kernel(float* __restrict__ out) {
    int b = blockIdx.x, tid = threadIdx.x;   // 128 threads
    __shared__ float red[128];
    float ls = 0.f;
#pragma unroll
    for (int k = 0; k < 4; ++k) ls += g_Lpart[(size_t)(k * 128 + tid) * BATCH + b];
    red[tid] = ls;
    __syncthreads();
    for (int o = 64; o; o >>= 1) { if (tid < o) red[tid] += red[tid + o]; __syncthreads(); }
    float invL = 1.0f / red[0];
    int d = tid * 4;
    float4 acc = make_float4(0.f, 0.f, 0.f, 0.f);
#pragma unroll
    for (int sp = 0; sp < SPLITS; ++sp) {
        const float4 v = *(const float4*)&g_part2[((size_t)sp * BATCH + b) * DIM + d];
        acc.x += v.x; acc.y += v.y; acc.z += v.z; acc.w += v.w;
    }
    acc.x *= invL; acc.y *= invL; acc.z *= invL; acc.w *= invL;
    *(float4*)&out[(size_t)b * DIM + d] = acc;
}

// ---------------------------------------------------------------------------
extern "C" void kernel_launch(void* const* d_in, const int* in_sizes, int n_in,
                              void* d_out, int out_size) {
    const float* x = (const float*)d_in[0];
    const float* mb = (const float*)d_in[1];
    float* out = (float*)d_out;
    (void)in_sizes; (void)n_in; (void)out_size;

    cudaFuncSetAttribute(gemm1_kernel, cudaFuncAttributeMaxDynamicSharedMemorySize, SMEM_BYTES);
    cudaFuncSetAttribute(gemm2_kernel, cudaFuncAttributeMaxDynamicSharedMemorySize, SMEM_BYTES);

    pack_x_kernel<<<BATCH / 8, 256>>>(x);
    pack_mb_kernel<<<dim3(SIZE / 32, DIM / 32), 256>>>(mb);
    mbnorm_reduce_kernel<<<SIZE / 256, 256>>>();
    gemm1_kernel<<<dim3(BATCH / AROWS, SIZE / BROWS), THREADS, SMEM_BYTES>>>();
    gemm2_kernel<<<dim3(BATCH / AROWS, DIM / BROWS, SPLITS), THREADS, SMEM_BYTES>>>();
    combine_kernel<<<BATCH, 128>>>(out);
}

// round 17
// speedup vs baseline: 3.5568x; 1.0239x over previous
#include <cuda_runtime.h>
#include <cuda_fp16.h>
#include <cstdint>
#include <cstddef>

#define BATCH 1024
#define SIZE  65536
#define DIM   512
#define SPLITS 32
#define KSPLIT (SIZE / SPLITS)        // 2048

#define RBYTES 128                    // dense 64-half rows, 8-slot XOR swizzle (row&7)
#define TILE_BYTES (128 * RBYTES)     // 16384
#define STAGE_BYTES (2 * TILE_BYTES)  // 32768 (A+B)
#define NSTAGE 3
#define SMEM_BYTES (NSTAGE * STAGE_BYTES) // 98304
#define THREADS 128
#define NCH1 (DIM / 64)               // 8
#define NCH2 (KSPLIT / 64)            // 32

// ---------------- device scratch (allocation-free) ----------------
__device__ float g_minv[SIZE];
__device__ float g_ssq[(size_t)SIZE * 16];                     //   4 MB partial sumsq
__device__ __align__(16) __half g_xp[(size_t)BATCH * DIM];     //   1 MB (plain k-major)
__device__ __align__(16) __half g_mb1[(size_t)SIZE * DIM];     //  64 MB (plain k-major)
__device__ __align__(16) __half g_mbT[(size_t)DIM * SIZE];     //  64 MB (plain k-major)
__device__ __align__(16) __half g_P[(size_t)BATCH * SIZE];     // 128 MB (plain k-major)
__device__ float g_Lpart[(size_t)(SIZE / 128) * BATCH];        //   2 MB
__device__ float g_part2[(size_t)SPLITS * BATCH * DIM];        //  64 MB

// ---------------- helpers ----------------
__device__ __forceinline__ uint32_t smem_to_u32(const void* p) {
    uint32_t a;
    asm("{ .reg .u64 t; cvta.to.shared.u64 t, %1; cvt.u32.u64 %0, t; }" : "=r"(a) : "l"(p));
    return a;
}
__device__ __forceinline__ void cp16(uint32_t s, const void* g) {
    asm volatile("cp.async.cg.shared.global [%0], [%1], 16;" :: "r"(s), "l"(g));
}
__device__ __forceinline__ void cp_commit() { asm volatile("cp.async.commit_group;"); }
__device__ __forceinline__ float ex2f(float x) {
    float r;
    asm("ex2.approx.f32 %0, %1;" : "=f"(r) : "f"(x));
    return r;
}
__device__ __forceinline__ void ldsm4(uint32_t* r, uint32_t addr) {
    asm volatile("ldmatrix.sync.aligned.m8n8.x4.shared.b16 {%0,%1,%2,%3}, [%4];"
                 : "=r"(r[0]), "=r"(r[1]), "=r"(r[2]), "=r"(r[3]) : "r"(addr));
}
__device__ __forceinline__ void mma_f16(float* c, const uint32_t* a,
                                        uint32_t b0, uint32_t b1) {
    asm volatile(
        "mma.sync.aligned.m16n8k16.row.col.f32.f16.f16.f32 "
        "{%0,%1,%2,%3}, {%4,%5,%6,%7}, {%8,%9}, {%0,%1,%2,%3};"
        : "+f"(c[0]), "+f"(c[1]), "+f"(c[2]), "+f"(c[3])
        : "r"(a[0]), "r"(a[1]), "r"(a[2]), "r"(a[3]), "r"(b0), "r"(b1));
}

// ---------------- kernel 1: pack x -> fp16 (norm fused), plain k-major ----------------
__global__ void pack_x_kernel(const float* __restrict__ x) {
    int m = blockIdx.x * 8 + (threadIdx.x >> 5);   // warp per row
    int l = threadIdx.x & 31;
    const float4* a = reinterpret_cast<const float4*>(x + (size_t)m * DIM);
    float4 v[4]; float ss = 0.f;
#pragma unroll
    for (int j = 0; j < 4; ++j) {
        v[j] = a[l + 32 * j];
        ss += v[j].x * v[j].x + v[j].y * v[j].y + v[j].z * v[j].z + v[j].w * v[j].w;
    }
#pragma unroll
    for (int o = 16; o; o >>= 1) ss += __shfl_xor_sync(0xffffffffu, ss, o);
    float s = 8.0f * rsqrtf(fmaxf(ss, 1e-24f));
#pragma unroll
    for (int j = 0; j < 4; ++j) {
        int d = 4 * (l + 32 * j);
        *(__half2*)&g_xp[(size_t)m * DIM + d]     = __floats2half2_rn(v[j].x * s, v[j].y * s);
        *(__half2*)&g_xp[(size_t)m * DIM + d + 2] = __floats2half2_rn(v[j].z * s, v[j].w * s);
    }
}

// ---------------- kernel 2: pack mb -> g_mb1 + g_mbT (plain) + partial sumsq ----------
__global__ void pack_mb_kernel(const float* __restrict__ mbk) {
    __shared__ float t[32][33];
    int s0 = blockIdx.x << 5, d0 = blockIdx.y << 5;
    int tp = threadIdx.x & 15, ty = threadIdx.x >> 4;   // 256 threads
    float ss[2];
#pragma unroll
    for (int k = 0; k < 2; ++k) {
        int r = ty + 16 * k;
        float2 v = *(const float2*)&mbk[(size_t)(s0 + r) * DIM + d0 + 2 * tp];
        t[r][2 * tp] = v.x; t[r][2 * tp + 1] = v.y;
        *(__half2*)&g_mb1[(size_t)(s0 + r) * DIM + d0 + 2 * tp] = __float22half2_rn(v);
        ss[k] = v.x * v.x + v.y * v.y;
    }
#pragma unroll
    for (int o = 8; o; o >>= 1) {
        ss[0] += __shfl_xor_sync(0xffffffffu, ss[0], o);
        ss[1] += __shfl_xor_sync(0xffffffffu, ss[1], o);
    }
    if (tp == 0) {
        g_ssq[(size_t)(s0 + ty) * 16 + blockIdx.y] = ss[0];
        g_ssq[(size_t)(s0 + ty + 16) * 16 + blockIdx.y] = ss[1];
    }
    __syncthreads();
#pragma unroll
    for (int k = 0; k < 2; ++k) {
        int dd = ty + 16 * k;
        float2 v = make_float2(t[2 * tp][dd], t[2 * tp + 1][dd]);
        *(__half2*)&g_mbT[(size_t)(d0 + dd) * SIZE + s0 + 2 * tp] = __float22half2_rn(v);
    }
}

// ---------------- kernel 3: reduce 16 partials -> inverse norm ----------------
__global__ void mbnorm_reduce_kernel() {
    int r = blockIdx.x * 256 + threadIdx.x;
    const float4* p = (const float4*)&g_ssq[(size_t)r * 16];
    float4 a = p[0], b = p[1], c = p[2], d = p[3];
    float s = (a.x + a.y + a.z + a.w) + (b.x + b.y + b.z + b.w)
            + (c.x + c.y + c.z + c.w) + (d.x + d.y + d.z + d.w);
    g_minv[r] = rsqrtf(fmaxf(s, 1e-24f));
}

// ---------------- GEMM machinery: 4 warps, warp tile 64x64, 64-k chunks ----------
// Smem swizzle: chunk' = chunk ^ (row & 7). ldmatrix phases read 8 consecutive
// rows at one k16 slot -> 8 distinct chunks: conflict-free. cp.async stores
// likewise full-permutation per row: conflict-free.
__device__ __forceinline__ void load_tiles(uint32_t sbase,
                                           const __half* __restrict__ Ag,
                                           const __half* __restrict__ Bg,
                                           size_t arow, size_t brow, int kpos, int tid) {
#pragma unroll
    for (int j = 0; j < 8; ++j) {                 // A: 128 rows x 8 granules
        int i = tid + THREADS * j;
        int row = i >> 3, gg = i & 7;
        cp16(sbase + row * RBYTES + ((gg ^ (row & 7)) << 4),
             Ag + (size_t)row * arow + kpos + gg * 8);
    }
#pragma unroll
    for (int j = 0; j < 8; ++j) {                 // B
        int i = tid + THREADS * j;
        int row = i >> 3, gg = i & 7;
        cp16(sbase + TILE_BYTES + row * RBYTES + ((gg ^ (row & 7)) << 4),
             Bg + (size_t)row * brow + kpos + gg * 8);
    }
}

__device__ __forceinline__ void compute_chunk(uint32_t As, uint32_t Bs,
                                              int wm, int wn, int lane,
                                              float c[4][8][4]) {
    // ldmatrix lane roles
    const int lm = lane & 15, hA = lane >> 4;               // A: row-within-16, k-half
    const int nB = (lane & 7) + ((lane >> 4) << 3);         // B: row-within-16
    const int hB = (lane >> 3) & 1;                         // B: k-half
    uint32_t aBase[4], bBase[4];
    int aSw[4], bSw[4];
#pragma unroll
    for (int mt = 0; mt < 4; ++mt) {
        int row = wm * 64 + mt * 16 + lm;
        aBase[mt] = As + row * RBYTES;
        aSw[mt] = row & 7;
    }
#pragma unroll
    for (int ntp = 0; ntp < 4; ++ntp) {
        int row = wn * 64 + ntp * 16 + nB;
        bBase[ntp] = Bs + row * RBYTES;
        bSw[ntp] = row & 7;
    }
#pragma unroll
    for (int j = 0; j < 4; ++j) {                 // four k16 steps per 64-k chunk
        uint32_t a[4][4], b[4][4];
#pragma unroll
        for (int mt = 0; mt < 4; ++mt)
            ldsm4(a[mt], aBase[mt] + ((((j << 1) + hA) ^ aSw[mt]) << 4));
#pragma unroll
        for (int ntp = 0; ntp < 4; ++ntp)
            ldsm4(b[ntp], bBase[ntp] + ((((j << 1) + hB) ^ bSw[ntp]) << 4));
#pragma unroll
        for (int mt = 0; mt < 4; ++mt)
#pragma unroll
            for (int ntp = 0; ntp < 4; ++ntp) {
                mma_f16(c[mt][2 * ntp],     a[mt], b[ntp][0], b[ntp][1]);
                mma_f16(c[mt][2 * ntp + 1], a[mt], b[ntp][2], b[ntp][3]);
            }
    }
}

__device__ __forceinline__ void gemm_mainloop(uint32_t sm32,
                                              const __half* __restrict__ Ag,
                                              const __half* __restrict__ Bg,
                                              size_t arow, size_t brow,
                                              int kbase, int nch, int tid,
                                              int wm, int wn, int lane,
                                              float c[4][8][4]) {
#pragma unroll
    for (int s = 0; s < 2; ++s) {
        load_tiles(sm32 + s * STAGE_BYTES, Ag, Bg, arow, brow, kbase + s * 64, tid);
        cp_commit();
    }
    for (int t = 0; t < nch; ++t) {
        if (t + 2 < nch) asm volatile("cp.async.wait_group 1;");
        else             asm volatile("cp.async.wait_group 0;");
        __syncthreads();   // stage t ready; stage (t+2)%3 free
        if (t + 2 < nch) {
            load_tiles(sm32 + ((t + 2) % 3) * STAGE_BYTES, Ag, Bg, arow, brow,
                       kbase + (t + 2) * 64, tid);
            cp_commit();
        }
        uint32_t As = sm32 + (t % 3) * STAGE_BYTES;
        compute_chunk(As, As + TILE_BYTES, wm, wn, lane, c);
    }
}

// ---------------- kernel 4: GEMM1 sims + exp epilogue -> g_P (plain), g_Lpart ----------
__global__ __launch_bounds__(THREADS, 2) void gemm1_kernel() {
    extern __shared__ char smc[];
    uint32_t sm32 = smem_to_u32(smc);
    int tid = threadIdx.x, lane = tid & 31, w = tid >> 5;
    int wm = w & 1, wn = w >> 1, g = lane >> 2, tg = lane & 3;
    int mblk = blockIdx.x, nblk = blockIdx.y;

    float c[4][8][4];
#pragma unroll
    for (int mt = 0; mt < 4; ++mt)
#pragma unroll
        for (int nt = 0; nt < 8; ++nt)
#pragma unroll
            for (int i = 0; i < 4; ++i) c[mt][nt][i] = 0.f;

    gemm_mainloop(sm32,
                  g_xp + (size_t)mblk * 128 * DIM,
                  g_mb1 + (size_t)nblk * 128 * DIM,
                  DIM, DIM, 0, NCH1, tid, wm, wn, lane, c);

    __syncthreads();                         // tiles dead; reuse smem
    float* smL = (float*)smc;                // [2][128] = 1024 B
    float* minv_s = (float*)(smc + 1024);    // [128]
    if (tid < 128) minv_s[tid] = g_minv[nblk * 128 + tid] * 1.44269504f; // fold log2e
    __syncthreads();

    float sl[4], sh[4];
#pragma unroll
    for (int mt = 0; mt < 4; ++mt) { sl[mt] = 0.f; sh[mt] = 0.f; }
#pragma unroll
    for (int mt = 0; mt < 4; ++mt) {
        int row0 = mblk * 128 + wm * 64 + mt * 16 + g;
        size_t b0 = (size_t)row0 * SIZE;
        size_t b8 = (size_t)(row0 + 8) * SIZE;
#pragma unroll
        for (int nt = 0; nt < 8; ++nt) {
            int col0 = wn * 64 + nt * 8 + 2 * tg;
            float m0 = minv_s[col0], m1 = minv_s[col0 + 1];
            float e0 = ex2f(c[mt][nt][0] * m0);
            float e1 = ex2f(c[mt][nt][1] * m1);
            float e2 = ex2f(c[mt][nt][2] * m0);
            float e3 = ex2f(c[mt][nt][3] * m1);
            sl[mt] += e0 + e1;
            sh[mt] += e2 + e3;
            size_t scol = (size_t)nblk * 128 + col0;     // plain k-major P
            *(__half2*)&g_P[b0 + scol] = __floats2half2_rn(e0, e1);
            *(__half2*)&g_P[b8 + scol] = __floats2half2_rn(e2, e3);
        }
    }
#pragma unroll
    for (int mt = 0; mt < 4; ++mt) {
        float vl = sl[mt], vh = sh[mt];
        vl += __shfl_xor_sync(0xffffffffu, vl, 1);
        vl += __shfl_xor_sync(0xffffffffu, vl, 2);
        vh += __shfl_xor_sync(0xffffffffu, vh, 1);
        vh += __shfl_xor_sync(0xffffffffu, vh, 2);
        if (tg == 0) {
            smL[wn * 128 + wm * 64 + mt * 16 + g] = vl;
            smL[wn * 128 + wm * 64 + mt * 16 + g + 8] = vh;
        }
    }
    __syncthreads();
    if (tid < 128)
        g_Lpart[(size_t)nblk * BATCH + mblk * 128 + tid] = smL[tid] + smL[128 + tid];
}

// ---------------- kernel 5: GEMM2 O = P @ mb (split-K partials) ----------------
__global__ __launch_bounds__(THREADS, 2) void gemm2_kernel() {
    extern __shared__ char smc[];
    uint32_t sm32 = smem_to_u32(smc);
    int tid = threadIdx.x, lane = tid & 31, w = tid >> 5;
    int wm = w & 1, wn = w >> 1, g = lane >> 2, tg = lane & 3;
    int mblk = blockIdx.x, nblk = blockIdx.y, sp = blockIdx.z;

    float c[4][8][4];
#pragma unroll
    for (int mt = 0; mt < 4; ++mt)
#pragma unroll
        for (int nt = 0; nt < 8; ++nt)
#pragma unroll
            for (int i = 0; i < 4; ++i) c[mt][nt][i] = 0.f;

    gemm_mainloop(sm32,
                  g_P + (size_t)mblk * 128 * SIZE,
                  g_mbT + (size_t)nblk * 128 * SIZE,
                  SIZE, SIZE, sp * KSPLIT, NCH2, tid, wm, wn, lane, c);

#pragma unroll
    for (int mt = 0; mt < 4; ++mt) {
        int b = mblk * 128 + wm * 64 + mt * 16 + g;
#pragma unroll
        for (int nt = 0; nt < 8; ++nt) {
            int d = nblk * 128 + wn * 64 + nt * 8 + 2 * tg;
            float* dst = &g_part2[((size_t)sp * BATCH + b) * DIM + d];
            *(float2*)dst = make_float2(c[mt][nt][0], c[mt][nt][1]);
            *(float2*)(dst + (size_t)8 * DIM) = make_float2(c[mt][nt][2], c[mt][nt][3]);
        }
    }
}

// ---------------- kernel 6: combine split-K partials, divide by L ----------------
__global__ void combine_kernel(float* __restrict__ out) {
    int b = blockIdx.x, tid = threadIdx.x;   // 128 threads
    __shared__ float red[128];
    float ls = 0.f;
#pragma unroll
    for (int k = 0; k < 4; ++k) ls += g_Lpart[(size_t)(k * 128 + tid) * BATCH + b];
    red[tid] = ls;
    __syncthreads();
    for (int o = 64; o; o >>= 1) { if (tid < o) red[tid] += red[tid + o]; __syncthreads(); }
    float invL = 1.0f / red[0];
    int d = tid * 4;
    float4 acc = make_float4(0.f, 0.f, 0.f, 0.f);
#pragma unroll
    for (int sp = 0; sp < SPLITS; ++sp) {
        const float4 v = *(const float4*)&g_part2[((size_t)sp * BATCH + b) * DIM + d];
        acc.x += v.x; acc.y += v.y; acc.z += v.z; acc.w += v.w;
    }
    acc.x *= invL; acc.y *= invL; acc.z *= invL; acc.w *= invL;
    *(float4*)&out[(size_t)b * DIM + d] = acc;
}

// ---------------------------------------------------------------------------
extern "C" void kernel_launch(void* const* d_in, const int* in_sizes, int n_in,
                              void* d_out, int out_size) {
    const float* x = (const float*)d_in[0];
    const float* mb = (const float*)d_in[1];
    float* out = (float*)d_out;
    (void)in_sizes; (void)n_in; (void)out_size;

    cudaFuncSetAttribute(gemm1_kernel, cudaFuncAttributeMaxDynamicSharedMemorySize, SMEM_BYTES);
    cudaFuncSetAttribute(gemm2_kernel, cudaFuncAttributeMaxDynamicSharedMemorySize, SMEM_BYTES);

    pack_x_kernel<<<BATCH / 8, 256>>>(x);
    pack_mb_kernel<<<dim3(SIZE / 32, DIM / 32), 256>>>(mb);
    mbnorm_reduce_kernel<<<SIZE / 256, 256>>>();
    gemm1_kernel<<<dim3(BATCH / 128, SIZE / 128), THREADS, SMEM_BYTES>>>();
    gemm2_kernel<<<dim3(BATCH / 128, DIM / 128, SPLITS), THREADS, SMEM_BYTES>>>();
    combine_kernel<<<BATCH, 128>>>(out);
}